// round 7
// baseline (speedup 1.0000x reference)
#include <cuda_runtime.h>

// VIN fully fused, channel-split dual-side layout.
//  r   = conv3x3(X, W_eff) + b_eff      (150-ch hidden layer collapsed)
//  qr  = conv3x3(r, q_w)   [5 channel-pairs, col-major qr2[j][x*65+y]]
//  v0  = max_l qr[l]
//  39x: v = max_l ( qr[l] + conv3x3(v, w[l]) )
// 512 threads: side A (tid<256) computes channels 0-5 (3 FFMA2 pairs),
// side B computes channels 6-9 (2 pairs). A writes partial max to SMEM;
// B combines with its register-held partial and writes new v. This keeps
// per-thread weight regs at 54/36 (not 90), giving ptxas pipelining slack
// under the 128-reg cap, with 4 warps/SMSP.

#define THREADS 512
#define NPX     4096
#define LQ      10
#define LH      150
#define QS      65                    // qr2 column stride (u64), odd
#define SV      67                    // v column stride (float), odd
#define PS      65                    // partial column stride (float), odd
#define RW      72                    // rbuf row stride (prologue)
#define RH      66
#define QPL     (64 * QS)             // qr2 plane stride (u64)
#define QR_F2   (5 * QPL + 16)
#define V_F     (66 * SV + 2)
#define SCRATCH_F 4752                // max(RH*RW=4752, 64*PS=4160)
#define SMEM_BYTES (QR_F2 * 8 + 2 * V_F * 4 + SCRATCH_F * 4)

typedef unsigned long long u64;

__device__ __forceinline__ u64 fma2(u64 a, u64 b, u64 c) {
    u64 d;
    asm("fma.rn.f32x2 %0, %1, %2, %3;" : "=l"(d) : "l"(a), "l"(b), "l"(c));
    return d;
}
__device__ __forceinline__ u64 dup2(float v) {
    u64 d;
    asm("mov.b64 %0, {%1, %1};" : "=l"(d) : "f"(v));
    return d;
}
__device__ __forceinline__ float maxpair(u64 a) {
    float lo, hi;
    asm("mov.b64 {%0, %1}, %2;" : "=f"(lo), "=f"(hi) : "l"(a));
    return fmaxf(lo, hi);
}

__global__ void __launch_bounds__(THREADS, 1)
vin_split_kernel(const float* __restrict__ X, const float* __restrict__ h_w,
                 const float* __restrict__ h_b, const float* __restrict__ r_w,
                 const float* __restrict__ q_w, const float* __restrict__ ww,
                 const int* __restrict__ kptr, float* __restrict__ out)
{
    extern __shared__ float smem[];
    u64*   qr2     = (u64*)smem;                 // [5][QPL] ch-pairs, col-major
    float* vA      = (float*)(qr2 + QR_F2);      // [66*SV] v, col-major
    float* vB      = vA + V_F;
    float* scratch = vB + V_F;                   // rbuf (prologue) / partial (loop)
    __shared__ float  s_weff[19];
    __shared__ float  s_qw[LQ * 9];
    __shared__ float2 s_wp[45];

    const int tid = threadIdx.x;
    const int b   = blockIdx.x;
    const float* Xb = X + (size_t)b * 2 * NPX;

    // ---- stage weights; collapse hidden layer ----
    if (tid < LQ * 9) s_qw[tid] = q_w[tid];
    if (tid < 45) {
        int j = tid / 9, t = tid % 9;
        s_wp[tid] = make_float2(ww[(2 * j) * 9 + t], ww[(2 * j + 1) * 9 + t]);
    }
    if (tid < 19) {
        float acc = 0.f;
        if (tid < 18) { for (int l = 0; l < LH; ++l) acc += r_w[l] * h_w[l * 18 + tid]; }
        else          { for (int l = 0; l < LH; ++l) acc += r_w[l] * h_b[l]; }
        s_weff[tid] = acc;
    }
    for (int i = tid; i < V_F; i += THREADS) { vA[i] = 0.f; vB[i] = 0.f; }
    for (int i = tid; i < RH * RW; i += THREADS) scratch[i] = 0.f;
    __syncthreads();

    // ---- r = conv3x3(X, W_eff) + b_eff (rbuf = scratch, row-major) ----
    for (int px = tid; px < NPX; px += THREADS) {
        int y = px >> 6, x = px & 63;
        float acc = s_weff[18];
        #pragma unroll
        for (int c = 0; c < 2; ++c)
            #pragma unroll
            for (int ky = 0; ky < 3; ++ky) {
                int iy = y - 1 + ky;
                if (iy < 0 || iy >= 64) continue;
                #pragma unroll
                for (int kx = 0; kx < 3; ++kx) {
                    int ix = x - 1 + kx;
                    if (ix < 0 || ix >= 64) continue;
                    acc += s_weff[c * 9 + ky * 3 + kx] * Xb[c * NPX + iy * 64 + ix];
                }
            }
        scratch[(y + 1) * RW + x + 1] = acc;
    }
    __syncthreads();

    // ---- qr pairs (col-major) + v0 into vA ----
    for (int px = tid; px < NPX; px += THREADS) {
        int y = px >> 6, x = px & 63;
        float n[9];
        #pragma unroll
        for (int ky = 0; ky < 3; ++ky)
            #pragma unroll
            for (int kx = 0; kx < 3; ++kx)
                n[ky * 3 + kx] = scratch[(y + ky) * RW + x + kx];
        float s[LQ];
        float vmax = -1e30f;
        #pragma unroll
        for (int l = 0; l < LQ; ++l) {
            float a = 0.f;
            #pragma unroll
            for (int t = 0; t < 9; ++t) a += s_qw[l * 9 + t] * n[t];
            s[l] = a;
            vmax = fmaxf(vmax, a);
        }
        #pragma unroll
        for (int j = 0; j < 5; ++j) {
            u64 p;
            asm("mov.b64 %0, {%1, %2};" : "=l"(p) : "f"(s[2 * j]), "f"(s[2 * j + 1]));
            qr2[j * QPL + x * QS + y] = p;
        }
        vA[(x + 1) * SV + (y + 1)] = vmax;
    }
    __syncthreads();

    const int side = tid >> 8;               // 0 = channels 0-5, 1 = channels 6-9
    const int t    = tid & 255;
    const int x    = t & 63;                 // column
    const int y0   = (t >> 6) << 4;          // band: 4 bands x 16 rows, exact
    const u64* qcol = qr2 + x * QS;
    float* partial  = scratch;               // [64*PS], col-major partial[x*PS+y]

    // ---- hoist this side's packed weights ----
    u64 wp[27];
    if (side == 0) {
        #pragma unroll
        for (int i = 0; i < 27; ++i) {
            float2 f = s_wp[i];
            asm("mov.b64 %0, {%1, %2};" : "=l"(wp[i]) : "f"(f.x), "f"(f.y));
        }
    } else {
        #pragma unroll
        for (int i = 0; i < 18; ++i) {
            float2 f = s_wp[27 + i];
            asm("mov.b64 %0, {%1, %2};" : "=l"(wp[i]) : "f"(f.x), "f"(f.y));
        }
    }

    const int k = kptr[0];
    float* cur = vA;
    float* alt = vB;

    // ---- value iteration ----
    for (int it = 0; it < k - 1; ++it) {
        const float* c0 = cur + x * SV;          // v column x-1
        const float* c1 = c0 + SV;               // x
        const float* c2 = c1 + SV;               // x+1
        float mB[16];                            // side B partial (regs)

        u64 np[3][3];
        #pragma unroll
        for (int r = 0; r < 3; ++r) {
            np[r][0] = dup2(c0[y0 + r]);
            np[r][1] = dup2(c1[y0 + r]);
            np[r][2] = dup2(c2[y0 + r]);
        }

        if (side == 0) {
            // ---- channels 0-5: 3 pairs, write partial max to SMEM ----
            #pragma unroll
            for (int yy = 0; yy < 16; ++yy) {
                const int y = y0 + yy;
                u64 a0 = qcol[y], a1 = qcol[QPL + y], a2 = qcol[2 * QPL + y];
                #pragma unroll
                for (int ky = 0; ky < 3; ++ky)
                    #pragma unroll
                    for (int kx = 0; kx < 3; ++kx) {
                        u64 nv = np[ky][kx];
                        a0 = fma2(nv, wp[ky * 3 + kx], a0);
                        a1 = fma2(nv, wp[9 + ky * 3 + kx], a1);
                        a2 = fma2(nv, wp[18 + ky * 3 + kx], a2);
                    }
                partial[x * PS + y] =
                    fmaxf(fmaxf(maxpair(a0), maxpair(a1)), maxpair(a2));
                if (yy < 15) {
                    #pragma unroll
                    for (int c = 0; c < 3; ++c) {
                        np[0][c] = np[1][c];
                        np[1][c] = np[2][c];
                    }
                    np[2][0] = dup2(c0[y0 + yy + 3]);
                    np[2][1] = dup2(c1[y0 + yy + 3]);
                    np[2][2] = dup2(c2[y0 + yy + 3]);
                }
            }
        } else {
            // ---- channels 6-9: 2 pairs, keep partial in registers ----
            #pragma unroll
            for (int yy = 0; yy < 16; ++yy) {
                const int y = y0 + yy;
                u64 a0 = qcol[3 * QPL + y], a1 = qcol[4 * QPL + y];
                #pragma unroll
                for (int ky = 0; ky < 3; ++ky)
                    #pragma unroll
                    for (int kx = 0; kx < 3; ++kx) {
                        u64 nv = np[ky][kx];
                        a0 = fma2(nv, wp[ky * 3 + kx], a0);
                        a1 = fma2(nv, wp[9 + ky * 3 + kx], a1);
                    }
                mB[yy] = fmaxf(maxpair(a0), maxpair(a1));
                if (yy < 15) {
                    #pragma unroll
                    for (int c = 0; c < 3; ++c) {
                        np[0][c] = np[1][c];
                        np[1][c] = np[2][c];
                    }
                    np[2][0] = dup2(c0[y0 + yy + 3]);
                    np[2][1] = dup2(c1[y0 + yy + 3]);
                    np[2][2] = dup2(c2[y0 + yy + 3]);
                }
            }
        }
        __syncthreads();     // A's partial visible; all reads of cur done

        if (side == 1) {
            float* wcol = alt + (x + 1) * SV;
            #pragma unroll
            for (int yy = 0; yy < 16; ++yy) {
                const int y = y0 + yy;
                wcol[y + 1] = fmaxf(mB[yy], partial[x * PS + y]);
            }
        }
        __syncthreads();     // alt fully written
        float* tmp = cur; cur = alt; alt = tmp;
    }

    // ---- output [B,1,64,64] from cur ----
    for (int px = tid; px < NPX; px += THREADS) {
        int y = px >> 6, xx = px & 63;
        out[(size_t)b * NPX + px] = cur[(xx + 1) * SV + (y + 1)];
    }
}

extern "C" void kernel_launch(void* const* d_in, const int* in_sizes, int n_in,
                              void* d_out, int out_size) {
    const float* X   = (const float*)d_in[0];
    const float* h_w = (const float*)d_in[1];
    const float* h_b = (const float*)d_in[2];
    const float* r_w = (const float*)d_in[3];
    const float* q_w = (const float*)d_in[4];
    const float* w_  = (const float*)d_in[5];
    const int*   k   = (const int*)d_in[6];

    int B = in_sizes[0] / (2 * NPX);   // 128

    cudaFuncSetAttribute(vin_split_kernel,
                         cudaFuncAttributeMaxDynamicSharedMemorySize, SMEM_BYTES);
    vin_split_kernel<<<B, THREADS, SMEM_BYTES>>>(X, h_w, h_b, r_w, q_w, w_, k,
                                                 (float*)d_out);
}

// round 8
// speedup vs baseline: 1.1337x; 1.1337x over previous
#include <cuda_runtime.h>

// VIN fully fused, FFMA2 channel pairs, 2-row unrolled pipeline.
//  r   = conv3x3(X, W_eff) + b_eff      (150-ch hidden layer collapsed)
//  qr  = conv3x3(r, q_w)   [5 ch-pairs, col-major ulonglong2, y-pairs packed]
//  v0  = max_l qr[l]
//  39x: v = max_l ( qr[l] + conv3x3(v, w[l]) )
// 256 threads (cap 255 regs). Thread = column x, 16-row band, processed as
// 8 groups of 2 rows: 5x LDS.128 (qr y-pair) + 90 FFMA2 over 10 independent
// accumulator chains + 6 window LDS. Double-buffered v, 1 barrier/iter.

#define THREADS 256
#define NPX     4096
#define LQ      10
#define LH      150
#define QS2     33                   // qr column stride in ulonglong2 (528B, odd)
#define QPL2    (64 * QS2)           // qr plane stride (ulonglong2) = 2112
#define SV      67                   // v column stride (float), odd
#define V_F     (66 * SV + 2)        // 4424
#define RW      72                   // rbuf row stride (floats)
#define RH      66
#define RB_F    (RH * RW)            // 4752 >= V_F, vB aliases rbuf
#define SMEM_BYTES (5 * QPL2 * 16 + V_F * 4 + RB_F * 4)   // ~205.7 KB

typedef unsigned long long u64;

__device__ __forceinline__ u64 fma2(u64 a, u64 b, u64 c) {
    u64 d;
    asm("fma.rn.f32x2 %0, %1, %2, %3;" : "=l"(d) : "l"(a), "l"(b), "l"(c));
    return d;
}
__device__ __forceinline__ u64 dup2(float v) {
    u64 d;
    asm("mov.b64 %0, {%1, %1};" : "=l"(d) : "f"(v));
    return d;
}
__device__ __forceinline__ float maxpair(u64 a) {
    float lo, hi;
    asm("mov.b64 {%0, %1}, %2;" : "=f"(lo), "=f"(hi) : "l"(a));
    return fmaxf(lo, hi);
}

__global__ void __launch_bounds__(THREADS, 1)
vin_pipe_kernel(const float* __restrict__ X, const float* __restrict__ h_w,
                const float* __restrict__ h_b, const float* __restrict__ r_w,
                const float* __restrict__ q_w, const float* __restrict__ ww,
                const int* __restrict__ kptr, float* __restrict__ out)
{
    extern __shared__ float smem[];
    ulonglong2* qr2 = (ulonglong2*)smem;            // [5][QPL2] ch-pairs
    float* vA   = (float*)(qr2 + 5 * QPL2);         // [V_F] v, col-major
    float* vB   = vA + V_F;                          // [RB_F], aliases rbuf
    float* rbuf = vB;                                // prologue only
    __shared__ float  s_weff[19];
    __shared__ float  s_qw[LQ * 9];
    __shared__ float2 s_wp[45];

    const int tid = threadIdx.x;
    const int b   = blockIdx.x;
    const float* Xb = X + (size_t)b * 2 * NPX;

    // ---- stage weights; collapse hidden layer ----
    if (tid < LQ * 9) s_qw[tid] = q_w[tid];
    if (tid < 45) {
        int j = tid / 9, t = tid % 9;
        s_wp[tid] = make_float2(ww[(2 * j) * 9 + t], ww[(2 * j + 1) * 9 + t]);
    }
    if (tid < 19) {
        float acc = 0.f;
        if (tid < 18) { for (int l = 0; l < LH; ++l) acc += r_w[l] * h_w[l * 18 + tid]; }
        else          { for (int l = 0; l < LH; ++l) acc += r_w[l] * h_b[l]; }
        s_weff[tid] = acc;
    }
    for (int i = tid; i < V_F; i += THREADS) vA[i] = 0.f;
    for (int i = tid; i < RB_F; i += THREADS) rbuf[i] = 0.f;
    __syncthreads();

    // ---- r = conv3x3(X, W_eff) + b_eff (into rbuf, row-major) ----
    for (int px = tid; px < NPX; px += THREADS) {
        int y = px >> 6, x = px & 63;
        float acc = s_weff[18];
        #pragma unroll
        for (int c = 0; c < 2; ++c)
            #pragma unroll
            for (int ky = 0; ky < 3; ++ky) {
                int iy = y - 1 + ky;
                if (iy < 0 || iy >= 64) continue;
                #pragma unroll
                for (int kx = 0; kx < 3; ++kx) {
                    int ix = x - 1 + kx;
                    if (ix < 0 || ix >= 64) continue;
                    acc += s_weff[c * 9 + ky * 3 + kx] * Xb[c * NPX + iy * 64 + ix];
                }
            }
        rbuf[(y + 1) * RW + x + 1] = acc;
    }
    __syncthreads();

    // ---- qr pairs (col-major u64 slots) + v0 into vA ----
    {
        u64* qru = (u64*)qr2;
        for (int px = tid; px < NPX; px += THREADS) {
            int y = px >> 6, x = px & 63;
            float n[9];
            #pragma unroll
            for (int ky = 0; ky < 3; ++ky)
                #pragma unroll
                for (int kx = 0; kx < 3; ++kx)
                    n[ky * 3 + kx] = rbuf[(y + ky) * RW + x + kx];
            float s[LQ];
            float vmax = -1e30f;
            #pragma unroll
            for (int l = 0; l < LQ; ++l) {
                float a = 0.f;
                #pragma unroll
                for (int t = 0; t < 9; ++t) a += s_qw[l * 9 + t] * n[t];
                s[l] = a;
                vmax = fmaxf(vmax, a);
            }
            #pragma unroll
            for (int j = 0; j < 5; ++j) {
                u64 p;
                asm("mov.b64 %0, {%1, %2};" : "=l"(p) : "f"(s[2 * j]), "f"(s[2 * j + 1]));
                qru[(j * QPL2 + x * QS2) * 2 + y] = p;
            }
            vA[(x + 1) * SV + (y + 1)] = vmax;
        }
    }
    __syncthreads();

    // ---- zero vB (it aliased rbuf; ghosts must be 0) ----
    for (int i = tid; i < RB_F; i += THREADS) vB[i] = 0.f;

    // ---- hoist 45 packed weights into registers ----
    u64 wp[45];
    #pragma unroll
    for (int i = 0; i < 45; ++i) {
        float2 f = s_wp[i];
        asm("mov.b64 %0, {%1, %2};" : "=l"(wp[i]) : "f"(f.x), "f"(f.y));
    }

    const int k  = kptr[0];
    const int x  = tid & 63;                  // column
    const int y0 = (tid >> 6) << 4;           // band: 4 bands x 16 rows, exact
    const ulonglong2* qcol = qr2 + x * QS2;
    float* cur = vA;
    float* alt = vB;
    __syncthreads();                           // vB zeroed

    // ---- value iteration: 8 groups of 2 rows, 10 indep FFMA2 chains ----
    for (int it = 0; it < k - 1; ++it) {
        const float* c0 = cur + x * SV;        // v column x-1 (ghost-shifted)
        const float* c1 = c0 + SV;             // x
        const float* c2 = c1 + SV;             // x+1
        float* wcol = alt + (x + 1) * SV;

        // window rows y0-1..y0+2 -> v indices y0..y0+3, duplicated pairs
        u64 r0[3], r1[3], r2[3], r3[3];
        r0[0] = dup2(c0[y0]);     r0[1] = dup2(c1[y0]);     r0[2] = dup2(c2[y0]);
        r1[0] = dup2(c0[y0 + 1]); r1[1] = dup2(c1[y0 + 1]); r1[2] = dup2(c2[y0 + 1]);
        r2[0] = dup2(c0[y0 + 2]); r2[1] = dup2(c1[y0 + 2]); r2[2] = dup2(c2[y0 + 2]);
        r3[0] = dup2(c0[y0 + 3]); r3[1] = dup2(c1[y0 + 3]); r3[2] = dup2(c2[y0 + 3]);

        #pragma unroll
        for (int g = 0; g < 8; ++g) {
            const int Y = y0 + 2 * g;
            // batched qr loads: one LDS.128 per channel pair covers rows Y,Y+1
            u64 aA[5], aB[5];
            #pragma unroll
            for (int j = 0; j < 5; ++j) {
                ulonglong2 q = qcol[j * QPL2 + (Y >> 1)];
                aA[j] = q.x;
                aB[j] = q.y;
            }
            // 10 independent chains: row A uses r0,r1,r2; row B uses r1,r2,r3
            #pragma unroll
            for (int j = 0; j < 5; ++j)
                #pragma unroll
                for (int kx = 0; kx < 3; ++kx) {
                    aA[j] = fma2(r0[kx], wp[j * 9 + kx],     aA[j]);
                    aB[j] = fma2(r1[kx], wp[j * 9 + kx],     aB[j]);
                    aA[j] = fma2(r1[kx], wp[j * 9 + 3 + kx], aA[j]);
                    aB[j] = fma2(r2[kx], wp[j * 9 + 3 + kx], aB[j]);
                    aA[j] = fma2(r2[kx], wp[j * 9 + 6 + kx], aA[j]);
                    aB[j] = fma2(r3[kx], wp[j * 9 + 6 + kx], aB[j]);
                }
            float mA = maxpair(aA[0]), mB = maxpair(aB[0]);
            #pragma unroll
            for (int j = 1; j < 5; ++j) {
                mA = fmaxf(mA, maxpair(aA[j]));
                mB = fmaxf(mB, maxpair(aB[j]));
            }
            wcol[Y + 1] = mA;
            wcol[Y + 2] = mB;
            if (g < 7) {                       // slide window down 2 rows
                #pragma unroll
                for (int c = 0; c < 3; ++c) { r0[c] = r2[c]; r1[c] = r3[c]; }
                r2[0] = dup2(c0[Y + 4]); r2[1] = dup2(c1[Y + 4]); r2[2] = dup2(c2[Y + 4]);
                r3[0] = dup2(c0[Y + 5]); r3[1] = dup2(c1[Y + 5]); r3[2] = dup2(c2[Y + 5]);
            }
        }
        __syncthreads();                       // alt fully written
        float* tmp = cur; cur = alt; alt = tmp;
    }

    // ---- output [B,1,64,64] from cur ----
    for (int px = tid; px < NPX; px += THREADS) {
        int y = px >> 6, xx = px & 63;
        out[(size_t)b * NPX + px] = cur[(xx + 1) * SV + (y + 1)];
    }
}

extern "C" void kernel_launch(void* const* d_in, const int* in_sizes, int n_in,
                              void* d_out, int out_size) {
    const float* X   = (const float*)d_in[0];
    const float* h_w = (const float*)d_in[1];
    const float* h_b = (const float*)d_in[2];
    const float* r_w = (const float*)d_in[3];
    const float* q_w = (const float*)d_in[4];
    const float* w_  = (const float*)d_in[5];
    const int*   k   = (const int*)d_in[6];

    int B = in_sizes[0] / (2 * NPX);   // 128

    cudaFuncSetAttribute(vin_pipe_kernel,
                         cudaFuncAttributeMaxDynamicSharedMemorySize, SMEM_BYTES);
    vin_pipe_kernel<<<B, THREADS, SMEM_BYTES>>>(X, h_w, h_b, r_w, q_w, w_, k,
                                                (float*)d_out);
}

// round 11
// speedup vs baseline: 1.1354x; 1.0015x over previous
#include <cuda_runtime.h>

// VIN fully fused — scalar-FFMA with uniform-register weights (rev c,
// third submission of the same experiment after two infra failures;
// functionally identical to rev a/b).
// FFMA2 (f32x2) measured HALF-RATE on sm_103a (R1 vs R6/R8) -> dropped.
// Loop weights live in __constant__; channel loop NOT unrolled so only 9
// uniform weights are live at a time -> ptxas can hold them in URs and emit
// FFMA R,R,UR,R (2 GPR reads -> rt 1, 2x fp32 throughput vs 3-reg FFMA).
//  r   = conv3x3(X, W_eff) + b_eff      (150-ch hidden layer collapsed)
//  qr  = conv3x3(r, q_w)   [10 planes, col-major qr[ch][x*68+y]]
//  v0  = max_l qr[l]
//  39x: v = max_l ( qr[l] + conv3x3(v, w[l]) )
// 512 threads: thread = column x, 8-row band. v col-major stride 67
// (conflict-free scalar LDS); qr col stride 68 floats = 17 float4 (odd) ->
// conflict-free LDS.128. Double-buffered v, 1 barrier/iter.

#define THREADS 512
#define NPX     4096
#define LQ      10
#define LH      150
#define QCS     68                    // qr column stride (floats): 17 float4, odd
#define PPL     (64 * QCS)            // qr plane stride = 4352 floats
#define SV      67                    // v column stride (floats), odd
#define V_F     (66 * SV + 2)         // 4424
#define RW      72                    // rbuf row stride (prologue)
#define RB_F    (66 * RW)             // 4752 >= V_F; vB aliases rbuf
#define SMEM_BYTES ((LQ * PPL + V_F + RB_F) * 4)    // ~205.8 KB

__constant__ float c_wvi[LQ * 9];     // value-iteration weights (uniform)

__global__ void __launch_bounds__(THREADS, 1)
vin_urc_kernel(const float* __restrict__ X, const float* __restrict__ h_w,
               const float* __restrict__ h_b, const float* __restrict__ r_w,
               const float* __restrict__ q_w, const float* __restrict__ ww,
               const int* __restrict__ kptr, float* __restrict__ out)
{
    extern __shared__ float smem[];
    float* qr = smem;                  // [10][PPL] col-major planes
    float* vA = qr + LQ * PPL;         // [V_F] v, col-major, ghost border = 0
    float* vB = vA + V_F;              // [RB_F]; aliases rbuf
    float* rbuf = vB;                  // prologue only, row-major [66][72]
    __shared__ float s_weff[19];
    __shared__ float s_qw[LQ * 9];

    const int tid = threadIdx.x;
    const int b   = blockIdx.x;
    const float* Xb = X + (size_t)b * 2 * NPX;

    // ---- stage prologue weights; collapse hidden layer ----
    if (tid < LQ * 9) s_qw[tid] = q_w[tid];
    if (tid < 19) {
        float acc = 0.f;
        if (tid < 18) { for (int l = 0; l < LH; ++l) acc += r_w[l] * h_w[l * 18 + tid]; }
        else          { for (int l = 0; l < LH; ++l) acc += r_w[l] * h_b[l]; }
        s_weff[tid] = acc;
    }
    for (int i = tid; i < V_F; i += THREADS) vA[i] = 0.f;
    for (int i = tid; i < RB_F; i += THREADS) rbuf[i] = 0.f;
    __syncthreads();

    // ---- r = conv3x3(X, W_eff) + b_eff (rbuf row-major; coalesced X reads) ----
    for (int px = tid; px < NPX; px += THREADS) {
        int y = px >> 6, x = px & 63;
        float acc = s_weff[18];
        #pragma unroll
        for (int c = 0; c < 2; ++c)
            #pragma unroll
            for (int ky = 0; ky < 3; ++ky) {
                int iy = y - 1 + ky;
                if (iy < 0 || iy >= 64) continue;
                #pragma unroll
                for (int kx = 0; kx < 3; ++kx) {
                    int ix = x - 1 + kx;
                    if (ix < 0 || ix >= 64) continue;
                    acc += s_weff[c * 9 + ky * 3 + kx] * Xb[c * NPX + iy * 64 + ix];
                }
            }
        rbuf[(y + 1) * RW + x + 1] = acc;
    }
    __syncthreads();

    // ---- qr planes (col-major) + v0 into vA; y-major px mapping so the
    //      qr/vA stores are column-contiguous (conflict-free) ----
    for (int idx = tid; idx < NPX; idx += THREADS) {
        int x = idx >> 6, y = idx & 63;
        float n[9];
        #pragma unroll
        for (int ky = 0; ky < 3; ++ky)
            #pragma unroll
            for (int kx = 0; kx < 3; ++kx)
                n[ky * 3 + kx] = rbuf[(y + ky) * RW + x + kx];
        float vmax = -1e30f;
        #pragma unroll
        for (int l = 0; l < LQ; ++l) {
            float a = 0.f;
            #pragma unroll
            for (int t = 0; t < 9; ++t) a += s_qw[l * 9 + t] * n[t];
            qr[l * PPL + x * QCS + y] = a;
            vmax = fmaxf(vmax, a);
        }
        vA[(x + 1) * SV + (y + 1)] = vmax;
    }
    __syncthreads();

    // ---- zero vB (aliased rbuf; ghost border must be 0) ----
    for (int i = tid; i < RB_F; i += THREADS) vB[i] = 0.f;

    const int k  = kptr[0];
    const int x  = tid & 63;              // column
    const int y0 = (tid >> 6) << 3;       // band: 8 bands x 8 rows, exact
    const float* qc = qr + x * QCS + y0;
    float* cur = vA;
    float* alt = vB;
    __syncthreads();                      // vB zeroed

    // ---- value iteration ----
    for (int it = 0; it < k - 1; ++it) {
        const float* p0 = cur + x * SV + y0;        // v col x-1, rows y0-1..
        const float* p1 = p0 + SV;                  // x
        const float* p2 = p1 + SV;                  // x+1
        // window: 3 cols x 10 rows in registers (conflict-free scalar LDS)
        float wn0[10], wn1[10], wn2[10];
        #pragma unroll
        for (int j = 0; j < 10; ++j) {
            wn0[j] = p0[j]; wn1[j] = p1[j]; wn2[j] = p2[j];
        }
        float m[8];
        #pragma unroll
        for (int y = 0; y < 8; ++y) m[y] = -1e30f;

        #pragma unroll 1                  // keep only 9 uniform weights live
        for (int ch = 0; ch < LQ; ++ch) {
            const float* qp = qc + ch * PPL;
            float4 qa = *(const float4*)(qp);
            float4 qb = *(const float4*)(qp + 4);
            float qf[8] = {qa.x, qa.y, qa.z, qa.w, qb.x, qb.y, qb.z, qb.w};
            const float* cw = c_wvi + ch * 9;       // const-bank, uniform
            float c0 = cw[0], c1 = cw[1], c2 = cw[2];
            float c3 = cw[3], c4 = cw[4], c5 = cw[5];
            float c6 = cw[6], c7 = cw[7], c8 = cw[8];
            #pragma unroll
            for (int y = 0; y < 8; ++y) {
                float a = fmaf(c0, wn0[y],     qf[y]);
                a = fmaf(c1, wn1[y],     a);
                a = fmaf(c2, wn2[y],     a);
                a = fmaf(c3, wn0[y + 1], a);
                a = fmaf(c4, wn1[y + 1], a);
                a = fmaf(c5, wn2[y + 1], a);
                a = fmaf(c6, wn0[y + 2], a);
                a = fmaf(c7, wn1[y + 2], a);
                a = fmaf(c8, wn2[y + 2], a);
                m[y] = fmaxf(m[y], a);
            }
        }
        float* wc = alt + (x + 1) * SV + y0 + 1;
        #pragma unroll
        for (int y = 0; y < 8; ++y) wc[y] = m[y];
        __syncthreads();                  // alt complete; cur reads done
        float* t = cur; cur = alt; alt = t;
    }

    // ---- output [B,1,64,64] from cur ----
    for (int px = tid; px < NPX; px += THREADS) {
        int y = px >> 6, xx = px & 63;
        out[(size_t)b * NPX + px] = cur[(xx + 1) * SV + (y + 1)];
    }
}

extern "C" void kernel_launch(void* const* d_in, const int* in_sizes, int n_in,
                              void* d_out, int out_size) {
    const float* X   = (const float*)d_in[0];
    const float* h_w = (const float*)d_in[1];
    const float* h_b = (const float*)d_in[2];
    const float* r_w = (const float*)d_in[3];
    const float* q_w = (const float*)d_in[4];
    const float* w_  = (const float*)d_in[5];
    const int*   k   = (const int*)d_in[6];

    int B = in_sizes[0] / (2 * NPX);   // 128

    // stage loop weights into constant memory (async D2D; graph-capturable)
    cudaMemcpyToSymbolAsync(c_wvi, w_, LQ * 9 * sizeof(float), 0,
                            cudaMemcpyDeviceToDevice, 0);

    cudaFuncSetAttribute(vin_urc_kernel,
                         cudaFuncAttributeMaxDynamicSharedMemorySize, SMEM_BYTES);
    vin_urc_kernel<<<B, THREADS, SMEM_BYTES>>>(X, h_w, h_b, r_w, q_w, w_, k,
                                               (float*)d_out);
}

// round 12
// speedup vs baseline: 1.4362x; 1.2649x over previous
#include <cuda_runtime.h>
#include <cuda_fp16.h>

// VIN fully fused — HFMA2 (fp16x2) inner loop, channel pairs in lanes.
// fp32 FFMA is rt-2-capped on sm_103a (R1/R6/R11 all hit the same 5760
// cyc/iter wall); HFMA2 is full-rate with 2 MACs/inst -> 2x.
//  r   = conv3x3(X, W_eff) + b_eff      (fp32, 150-ch hidden collapsed)
//  qr  = conv3x3(r, q_w)  fp32, quantized ONCE to half2 pairs (ch 2j,2j+1)
//  v0  = max_l qr[l]
//  39x: v = max_l ( qr[l] + conv3x3(v, w[l]) )   [fp16x2, qr as acc init]
// v stored duplicated (v,v) half2 col-major stride 67 (odd, conflict-free);
// qr col-major stride 68 half2 (16B-aligned rows for LDS.128).
// 512 threads: thread = column x, 8-row band. Double-buffer, 1 barrier/iter.

#define THREADS 512
#define NPX     4096
#define LQ      10
#define LH      150
#define QSH     68                    // qr col stride (half2 words); 17x16B, odd
#define PPLH    (64 * QSH)            // qr plane stride = 4352 half2
#define SVH     67                    // v col stride (half2 words), odd
#define V_FH    (66 * SVH + 2)        // 4424 half2
#define RW      72                    // rbuf row stride (fp32, prologue)
#define RB_F    (66 * RW)             // 4752 fp32 words; vB aliases rbuf
#define SMEM_BYTES ((5 * PPLH + V_FH) * 4 + RB_F * 4)   // ~121 KB

__global__ void __launch_bounds__(THREADS, 1)
vin_h2_kernel(const float* __restrict__ X, const float* __restrict__ h_w,
              const float* __restrict__ h_b, const float* __restrict__ r_w,
              const float* __restrict__ q_w, const float* __restrict__ ww,
              const int* __restrict__ kptr, float* __restrict__ out)
{
    extern __shared__ float smem[];
    __half2* qrh = (__half2*)smem;               // [5][PPLH] ch-pair planes
    __half2* vA  = qrh + 5 * PPLH;               // [V_FH] (v,v) pairs
    float*   rbuf = (float*)(vA + V_FH);         // [RB_F] fp32, prologue only
    __half2* vB  = (__half2*)rbuf;               // aliases rbuf (V_FH <= RB_F)
    __shared__ float   s_weff[19];
    __shared__ float   s_qw[LQ * 9];
    __shared__ __half2 s_wph[45];                // packed loop weights

    const int tid = threadIdx.x;
    const int b   = blockIdx.x;
    const float* Xb = X + (size_t)b * 2 * NPX;

    // ---- stage weights; collapse hidden layer ----
    if (tid < LQ * 9) s_qw[tid] = q_w[tid];
    if (tid < 45) {
        int j = tid / 9, t = tid % 9;
        s_wph[tid] = __floats2half2_rn(ww[(2 * j) * 9 + t], ww[(2 * j + 1) * 9 + t]);
    }
    if (tid < 19) {
        float acc = 0.f;
        if (tid < 18) { for (int l = 0; l < LH; ++l) acc += r_w[l] * h_w[l * 18 + tid]; }
        else          { for (int l = 0; l < LH; ++l) acc += r_w[l] * h_b[l]; }
        s_weff[tid] = acc;
    }
    {
        const __half2 z = __float2half2_rn(0.f);
        for (int i = tid; i < V_FH; i += THREADS) vA[i] = z;
    }
    for (int i = tid; i < RB_F; i += THREADS) rbuf[i] = 0.f;
    __syncthreads();

    // ---- r = conv3x3(X, W_eff) + b_eff (fp32, rbuf row-major) ----
    for (int px = tid; px < NPX; px += THREADS) {
        int y = px >> 6, x = px & 63;
        float acc = s_weff[18];
        #pragma unroll
        for (int c = 0; c < 2; ++c)
            #pragma unroll
            for (int ky = 0; ky < 3; ++ky) {
                int iy = y - 1 + ky;
                if (iy < 0 || iy >= 64) continue;
                #pragma unroll
                for (int kx = 0; kx < 3; ++kx) {
                    int ix = x - 1 + kx;
                    if (ix < 0 || ix >= 64) continue;
                    acc += s_weff[c * 9 + ky * 3 + kx] * Xb[c * NPX + iy * 64 + ix];
                }
            }
        rbuf[(y + 1) * RW + x + 1] = acc;
    }
    __syncthreads();

    // ---- qr (fp32 -> half2 pairs, col-major) + v0 into vA ----
    for (int idx = tid; idx < NPX; idx += THREADS) {
        int x = idx >> 6, y = idx & 63;      // y-major: contiguous col stores
        float n[9];
        #pragma unroll
        for (int ky = 0; ky < 3; ++ky)
            #pragma unroll
            for (int kx = 0; kx < 3; ++kx)
                n[ky * 3 + kx] = rbuf[(y + ky) * RW + x + kx];
        float s[LQ];
        float vmax = -1e30f;
        #pragma unroll
        for (int l = 0; l < LQ; ++l) {
            float a = 0.f;
            #pragma unroll
            for (int t = 0; t < 9; ++t) a += s_qw[l * 9 + t] * n[t];
            s[l] = a;
            vmax = fmaxf(vmax, a);
        }
        #pragma unroll
        for (int j = 0; j < 5; ++j)
            qrh[j * PPLH + x * QSH + y] = __floats2half2_rn(s[2 * j], s[2 * j + 1]);
        vA[(x + 1) * SVH + (y + 1)] = __float2half2_rn(vmax);
    }
    __syncthreads();

    // ---- zero vB (aliased rbuf; ghost border must be 0) ----
    {
        const __half2 z = __float2half2_rn(0.f);
        for (int i = tid; i < V_FH; i += THREADS) vB[i] = z;
    }

    // ---- hoist 45 packed weights into registers (45 x 32-bit) ----
    __half2 wp[45];
    #pragma unroll
    for (int i = 0; i < 45; ++i) wp[i] = s_wph[i];

    const int k  = kptr[0];
    const int x  = tid & 63;              // column
    const int y0 = (tid >> 6) << 3;       // band: 8 bands x 8 rows, exact
    const __half2* qc = qrh + x * QSH + y0;
    __half2* cur = vA;
    __half2* alt = vB;
    __syncthreads();                      // vB zeroed

    // ---- value iteration ----
    for (int it = 0; it < k - 1; ++it) {
        const __half2* p0 = cur + x * SVH + y0;   // col x-1, rows y0-1..y0+8
        const __half2* p1 = p0 + SVH;             // x
        const __half2* p2 = p1 + SVH;             // x+1
        __half2 wn0[10], wn1[10], wn2[10];
        #pragma unroll
        for (int j = 0; j < 10; ++j) {
            wn0[j] = p0[j]; wn1[j] = p1[j]; wn2[j] = p2[j];
        }
        __half2 m[8];
        #pragma unroll
        for (int j = 0; j < 5; ++j) {
            // acc init = qr pair (2x LDS.128 over 8 rows)
            uint4 qa = *(const uint4*)(qc + j * PPLH);
            uint4 qb = *(const uint4*)(qc + j * PPLH + 4);
            __half2 qf[8];
            qf[0] = *(__half2*)&qa.x; qf[1] = *(__half2*)&qa.y;
            qf[2] = *(__half2*)&qa.z; qf[3] = *(__half2*)&qa.w;
            qf[4] = *(__half2*)&qb.x; qf[5] = *(__half2*)&qb.y;
            qf[6] = *(__half2*)&qb.z; qf[7] = *(__half2*)&qb.w;
            #pragma unroll
            for (int y = 0; y < 8; ++y) {
                __half2 a = qf[y];
                a = __hfma2(wn0[y],     wp[j * 9 + 0], a);
                a = __hfma2(wn1[y],     wp[j * 9 + 1], a);
                a = __hfma2(wn2[y],     wp[j * 9 + 2], a);
                a = __hfma2(wn0[y + 1], wp[j * 9 + 3], a);
                a = __hfma2(wn1[y + 1], wp[j * 9 + 4], a);
                a = __hfma2(wn2[y + 1], wp[j * 9 + 5], a);
                a = __hfma2(wn0[y + 2], wp[j * 9 + 6], a);
                a = __hfma2(wn1[y + 2], wp[j * 9 + 7], a);
                a = __hfma2(wn2[y + 2], wp[j * 9 + 8], a);
                m[y] = (j == 0) ? a : __hmax2(m[y], a);
            }
        }
        __half2* wc = alt + (x + 1) * SVH + y0 + 1;
        #pragma unroll
        for (int y = 0; y < 8; ++y) {
            // lanes hold (max even-ch, max odd-ch); fold -> duplicated (m,m)
            __half2 sw = __lowhigh2highlow(m[y]);
            wc[y] = __hmax2(m[y], sw);
        }
        __syncthreads();                  // alt complete; cur reads done
        __half2* t = cur; cur = alt; alt = t;
    }

    // ---- output [B,1,64,64] fp32 from cur ----
    for (int px = tid; px < NPX; px += THREADS) {
        int y = px >> 6, xx = px & 63;
        out[(size_t)b * NPX + px] = __low2float(cur[(xx + 1) * SVH + (y + 1)]);
    }
}

extern "C" void kernel_launch(void* const* d_in, const int* in_sizes, int n_in,
                              void* d_out, int out_size) {
    const float* X   = (const float*)d_in[0];
    const float* h_w = (const float*)d_in[1];
    const float* h_b = (const float*)d_in[2];
    const float* r_w = (const float*)d_in[3];
    const float* q_w = (const float*)d_in[4];
    const float* w_  = (const float*)d_in[5];
    const int*   k   = (const int*)d_in[6];

    int B = in_sizes[0] / (2 * NPX);   // 128

    cudaFuncSetAttribute(vin_h2_kernel,
                         cudaFuncAttributeMaxDynamicSharedMemorySize, SMEM_BYTES);
    vin_h2_kernel<<<B, THREADS, SMEM_BYTES>>>(X, h_w, h_b, r_w, q_w, w_, k,
                                              (float*)d_out);
}